// round 13
// baseline (speedup 1.0000x reference)
#include <cuda_runtime.h>
#include <cstdint>

#define TT  12
#define NN  50000
#define EE  800000
#define TN  (TT*NN)          /* 600000 */
#define FIN 128
#define HH  64

// ------------------------- static device scratch -------------------------
__device__ float d_xw[(size_t)TN*64];          // xs @ W_gcn
__device__ float d_cur[(size_t)TN*64];         // GCN output
__device__ float d_gicur[(size_t)TN*192];      // cur @ W_ih[:, :64]^T
__device__ float d_yring[(size_t)3*NN*192];    // y = h @ Ws ring
__device__ float d_gring[3*NN];                // attention scalar ring
__device__ float d_dinv[TN];
__device__ int   d_cnt[TN];
__device__ int   d_fill[TN];
__device__ int   d_rowptr[TN];
__device__ int   d_ebuf[(size_t)TT*EE];
__device__ float d_WcT[64*192];                // [k][j] = W_ih[j][k]          (cur half)
__device__ float d_WsQ[64*256];                // [k][0..191]=W_ih[j][64+k]; [k][192+c]=Q[c][k]
__device__ int   d_bsum[1024];

// ------------------------- helpers -------------------------
__device__ __forceinline__ void ffma2(unsigned long long& d,
                                      unsigned long long a,
                                      unsigned long long b)
{
    asm("fma.rn.f32x2 %0, %1, %2, %0;" : "+l"(d) : "l"(a), "l"(b));
}

__device__ __forceinline__ float2 u2f2(unsigned long long u)
{
    float2 f;
    asm("mov.b64 {%0,%1}, %2;" : "=f"(f.x), "=f"(f.y) : "l"(u));
    return f;
}

__device__ __forceinline__ float sigf(float x)
{
    return 1.0f / (1.0f + __expf(-x));
}

// ------------------------- weight prep -------------------------
__global__ void k_prep(const float* __restrict__ W_ih, const float* __restrict__ Q,
                       float* __restrict__ WcT, float* __restrict__ WsQ)
{
    for (int i = threadIdx.x; i < 64*192; i += 256) {
        int k = i / 192, j = i % 192;
        WcT[(size_t)k*192 + j] = W_ih[(size_t)j*128 + k];
        WsQ[(size_t)k*256 + j] = W_ih[(size_t)j*128 + 64 + k];
    }
    for (int i = threadIdx.x; i < 64*64; i += 256) {
        int k = i / 64, c = i % 64;
        WsQ[(size_t)k*256 + 192 + c] = Q[(size_t)c*64 + k];
    }
}

// ------------------------- CSR build -------------------------
__global__ void k_count(const int* __restrict__ ei, int* __restrict__ cnt)
{
    int e = blockIdx.x*256 + threadIdx.x;
    int t = blockIdx.y;
    if (e < EE) {
        int dst = ei[(size_t)t*2*EE + EE + e];
        atomicAdd(&cnt[t*NN + dst], 1);
    }
}

__global__ void k_scan1(const int* __restrict__ cnt, int* __restrict__ incl,
                        int* __restrict__ bsum, int n)
{
    __shared__ int ws[32];
    int tid  = threadIdx.x;
    int i    = blockIdx.x*1024 + tid;
    int lane = tid & 31, wid = tid >> 5;
    int v = (i < n) ? cnt[i] : 0;
    int x = v;
#pragma unroll
    for (int o = 1; o < 32; o <<= 1) {
        int y = __shfl_up_sync(0xffffffffu, x, o);
        if (lane >= o) x += y;
    }
    if (lane == 31) ws[wid] = x;
    __syncthreads();
    if (wid == 0) {
        int s = ws[lane];
#pragma unroll
        for (int o = 1; o < 32; o <<= 1) {
            int y = __shfl_up_sync(0xffffffffu, s, o);
            if (lane >= o) s += y;
        }
        ws[lane] = s;
    }
    __syncthreads();
    if (wid > 0) x += ws[wid-1];
    if (i < n) incl[i] = x;
    if (tid == 1023) bsum[blockIdx.x] = x;
}

__global__ void k_scan2(int* __restrict__ bsum, int nb)
{
    __shared__ int ws[32];
    int tid  = threadIdx.x;
    int lane = tid & 31, wid = tid >> 5;
    int v = (tid < nb) ? bsum[tid] : 0;
    int x = v;
#pragma unroll
    for (int o = 1; o < 32; o <<= 1) {
        int y = __shfl_up_sync(0xffffffffu, x, o);
        if (lane >= o) x += y;
    }
    if (lane == 31) ws[wid] = x;
    __syncthreads();
    if (wid == 0) {
        int s = ws[lane];
#pragma unroll
        for (int o = 1; o < 32; o <<= 1) {
            int y = __shfl_up_sync(0xffffffffu, s, o);
            if (lane >= o) s += y;
        }
        ws[lane] = s;
    }
    __syncthreads();
    if (wid > 0) x += ws[wid-1];
    if (tid < nb) bsum[tid] = x - v;   // exclusive
}

__global__ void k_scan3(const int* __restrict__ cnt, int* __restrict__ incl_then_rowptr,
                        const int* __restrict__ bsum, int* __restrict__ fill,
                        float* __restrict__ dinv, int n)
{
    int i = blockIdx.x*1024 + threadIdx.x;
    if (i < n) {
        int c  = cnt[i];
        int ex = incl_then_rowptr[i] - c + bsum[blockIdx.x];
        incl_then_rowptr[i] = ex;
        fill[i] = ex;
        dinv[i] = rsqrtf(1.0f + (float)c);
    }
}

__global__ void k_fill(const int* __restrict__ ei, int* __restrict__ fill,
                       int* __restrict__ ebuf)
{
    int e = blockIdx.x*256 + threadIdx.x;
    int t = blockIdx.y;
    if (e < EE) {
        int src = ei[(size_t)t*2*EE + e];
        int dst = ei[(size_t)t*2*EE + EE + e];
        int pos = atomicAdd(&fill[t*NN + dst], 1);
        ebuf[pos] = t*NN + src;
    }
}

// ------------------------- gather (GCN aggregation) -------------------------
__global__ void k_gather(const float* __restrict__ xw, const float* __restrict__ bg,
                         float* __restrict__ cur,
                         const int* __restrict__ rowptr, const int* __restrict__ cnt,
                         const float* __restrict__ dinv, const int* __restrict__ ebuf)
{
    int w    = blockIdx.x*8 + (threadIdx.x >> 5);
    int lane = threadIdx.x & 31;
    if (w >= TN) return;
    int start = rowptr[w];
    int c     = cnt[w];
    int col   = 2*lane;
    float2 a0 = make_float2(0.f, 0.f), a1 = a0, a2 = a0, a3 = a0;
    for (int b0 = 0; b0 < c; b0 += 32) {
        int rem  = c - b0;
        int mcnt = rem < 32 ? rem : 32;
        int   idx = (lane < mcnt) ? ebuf[start + b0 + lane] : 0;
        float dv  = (lane < mcnt) ? dinv[idx] : 0.f;
        int e = 0;
        for (; e + 4 <= mcnt; e += 4) {
            int g0 = __shfl_sync(0xffffffffu, idx, e);
            int g1 = __shfl_sync(0xffffffffu, idx, e+1);
            int g2 = __shfl_sync(0xffffffffu, idx, e+2);
            int g3 = __shfl_sync(0xffffffffu, idx, e+3);
            float w0 = __shfl_sync(0xffffffffu, dv, e);
            float w1 = __shfl_sync(0xffffffffu, dv, e+1);
            float w2 = __shfl_sync(0xffffffffu, dv, e+2);
            float w3 = __shfl_sync(0xffffffffu, dv, e+3);
            float2 x0 = *(const float2*)&xw[(size_t)g0*64 + col];
            float2 x1 = *(const float2*)&xw[(size_t)g1*64 + col];
            float2 x2 = *(const float2*)&xw[(size_t)g2*64 + col];
            float2 x3 = *(const float2*)&xw[(size_t)g3*64 + col];
            a0.x += w0*x0.x; a0.y += w0*x0.y;
            a1.x += w1*x1.x; a1.y += w1*x1.y;
            a2.x += w2*x2.x; a2.y += w2*x2.y;
            a3.x += w3*x3.x; a3.y += w3*x3.y;
        }
        for (; e < mcnt; e++) {
            int   g  = __shfl_sync(0xffffffffu, idx, e);
            float wv = __shfl_sync(0xffffffffu, dv,  e);
            float2 x = *(const float2*)&xw[(size_t)g*64 + col];
            a0.x += wv*x.x; a0.y += wv*x.y;
        }
    }
    float ax = a0.x + a1.x + a2.x + a3.x;
    float ay = a0.y + a1.y + a2.y + a3.y;
    float ds = dinv[w];
    float2 s = *(const float2*)&xw[(size_t)w*64 + col];
    float2 o;
    o.x = ds*(ax + ds*s.x) + bg[col];
    o.y = ds*(ay + ds*s.y) + bg[col+1];
    *(float2*)&cur[(size_t)w*64 + col] = o;
}

// ------------------------- GEMM v5 (round-10 winner): coalesced fill + XOR-swizzled A panel -------------------------
#define BM 256
#define ASTRIDE 260
#define AOFF(k, r) ((k)*ASTRIDE + ((r) ^ ((((k) >> 2) & 7) << 2)))
#define BPOS(cp) (4*(cp) + ((((cp)) >> 2) << 2))   /* dup col-pair float offset */
#define GSM_BYTES ((64*ASTRIDE + 64*160) * 4)      /* 107520 B */

__global__ __launch_bounds__(256, 2)
void k_gemm(const float* __restrict__ A, const float* __restrict__ B,
            float* __restrict__ C, int M, int K, int ldb, int ldc,
            float* __restrict__ gbuf, const float* __restrict__ rv)
{
    extern __shared__ __align__(16) float smx[];
    float* As = smx;                    // [64][ASTRIDE] swizzled col-major
    float* Bs = smx + 64*ASTRIDE;       // [64][160] duplicated col pairs
    int tid   = threadIdx.x;
    int row0  = blockIdx.x * BM;
    int nb    = blockIdx.y * 64;
    int rbase = (tid >> 3) * 8;      // 8 rows (4 node pairs)
    int c0    = (tid & 7) * 8;       // 8 cols
    int cp0   = 4 * (tid & 7);       // col-pair base
    unsigned long long acc[4][8];
#pragma unroll
    for (int i = 0; i < 4; i++)
#pragma unroll
        for (int j = 0; j < 8; j++) acc[i][j] = 0ull;

    int wrp  = tid >> 5;
    int lane = tid & 31;
    int half = lane >> 4;
    int l4   = lane & 15;
    int sw   = (l4 & 7) << 2;

    for (int kk = 0; kk < K; kk += 64) {
        if (kk) __syncthreads();
        // A panel fill: per round a warp loads 2 rows x 64 cols coalesced
#pragma unroll
        for (int rr = 0; rr < 16; rr += 4) {
            float4 va[4];
#pragma unroll
            for (int u = 0; u < 4; u++) {
                int lr = wrp*32 + (rr + u)*2 + half;
                int gr = row0 + lr;
                va[u] = (gr < M) ? *(const float4*)&A[(size_t)gr*K + kk + 4*l4]
                                 : make_float4(0.f, 0.f, 0.f, 0.f);
            }
#pragma unroll
            for (int u = 0; u < 4; u++) {
                int lr  = wrp*32 + (rr + u)*2 + half;
                int rsw = lr ^ sw;
                As[(4*l4 + 0)*ASTRIDE + rsw] = va[u].x;
                As[(4*l4 + 1)*ASTRIDE + rsw] = va[u].y;
                As[(4*l4 + 2)*ASTRIDE + rsw] = va[u].z;
                As[(4*l4 + 3)*ASTRIDE + rsw] = va[u].w;
            }
        }
        // B panel: 64 rows x 64 cols, duplicated pairs
#pragma unroll
        for (int q = 0; q < 4; q++) {
            int idx = tid + q*256;
            int kb  = idx >> 4;
            int cq  = idx & 15;
            float4 w = *(const float4*)&B[(size_t)(kk + kb)*ldb + nb + cq*4];
            *(float4*)&Bs[kb*160 + BPOS(cq*2)]     = make_float4(w.x, w.x, w.y, w.y);
            *(float4*)&Bs[kb*160 + BPOS(cq*2 + 1)] = make_float4(w.z, w.z, w.w, w.w);
        }
        __syncthreads();
#pragma unroll
        for (int k = 0; k < 64; k++) {
            ulonglong2 a01 = *(const ulonglong2*)&As[AOFF(k, rbase)];
            ulonglong2 a23 = *(const ulonglong2*)&As[AOFF(k, rbase + 4)];
            ulonglong2 b0  = *(const ulonglong2*)&Bs[k*160 + BPOS(cp0)];
            ulonglong2 b1  = *(const ulonglong2*)&Bs[k*160 + BPOS(cp0) + 4];
            ulonglong2 b2  = *(const ulonglong2*)&Bs[k*160 + BPOS(cp0) + 8];
            ulonglong2 b3  = *(const ulonglong2*)&Bs[k*160 + BPOS(cp0) + 12];
            ffma2(acc[0][0], a01.x, b0.x); ffma2(acc[0][1], a01.x, b0.y);
            ffma2(acc[0][2], a01.x, b1.x); ffma2(acc[0][3], a01.x, b1.y);
            ffma2(acc[0][4], a01.x, b2.x); ffma2(acc[0][5], a01.x, b2.y);
            ffma2(acc[0][6], a01.x, b3.x); ffma2(acc[0][7], a01.x, b3.y);
            ffma2(acc[1][0], a01.y, b0.x); ffma2(acc[1][1], a01.y, b0.y);
            ffma2(acc[1][2], a01.y, b1.x); ffma2(acc[1][3], a01.y, b1.y);
            ffma2(acc[1][4], a01.y, b2.x); ffma2(acc[1][5], a01.y, b2.y);
            ffma2(acc[1][6], a01.y, b3.x); ffma2(acc[1][7], a01.y, b3.y);
            ffma2(acc[2][0], a23.x, b0.x); ffma2(acc[2][1], a23.x, b0.y);
            ffma2(acc[2][2], a23.x, b1.x); ffma2(acc[2][3], a23.x, b1.y);
            ffma2(acc[2][4], a23.x, b2.x); ffma2(acc[2][5], a23.x, b2.y);
            ffma2(acc[2][6], a23.x, b3.x); ffma2(acc[2][7], a23.x, b3.y);
            ffma2(acc[3][0], a23.y, b0.x); ffma2(acc[3][1], a23.y, b0.y);
            ffma2(acc[3][2], a23.y, b1.x); ffma2(acc[3][3], a23.y, b1.y);
            ffma2(acc[3][4], a23.y, b2.x); ffma2(acc[3][5], a23.y, b2.y);
            ffma2(acc[3][6], a23.y, b3.x); ffma2(acc[3][7], a23.y, b3.y);
        }
    }

    if (gbuf != nullptr && blockIdx.y == 3) {
        // score epilogue: g = sum_c rv[c]*tanh(y2[c]); cols split over 8 lanes
        float rr[8];
#pragma unroll
        for (int j = 0; j < 8; j++) rr[j] = rv[c0 + j];
#pragma unroll
        for (int i = 0; i < 4; i++) {
            float px = 0.f, py = 0.f;
#pragma unroll
            for (int j = 0; j < 8; j++) {
                float2 v = u2f2(acc[i][j]);
                px += rr[j] * tanhf(v.x);
                py += rr[j] * tanhf(v.y);
            }
            px += __shfl_down_sync(0xffffffffu, px, 4);
            py += __shfl_down_sync(0xffffffffu, py, 4);
            px += __shfl_down_sync(0xffffffffu, px, 2);
            py += __shfl_down_sync(0xffffffffu, py, 2);
            px += __shfl_down_sync(0xffffffffu, px, 1);
            py += __shfl_down_sync(0xffffffffu, py, 1);
            if ((tid & 7) == 0) {
                int n0 = row0 + rbase + 2*i;
                if (n0 < M)     gbuf[n0]     = px;
                if (n0 + 1 < M) gbuf[n0 + 1] = py;
            }
        }
        return;
    }

#pragma unroll
    for (int i = 0; i < 4; i++) {
        int n0 = row0 + rbase + 2*i;
        float2 v0 = u2f2(acc[i][0]), v1 = u2f2(acc[i][1]);
        float2 v2 = u2f2(acc[i][2]), v3 = u2f2(acc[i][3]);
        float2 v4 = u2f2(acc[i][4]), v5 = u2f2(acc[i][5]);
        float2 v6 = u2f2(acc[i][6]), v7 = u2f2(acc[i][7]);
        if (n0 < M) {
            *(float4*)&C[(size_t)n0*ldc + nb + c0]     = make_float4(v0.x, v1.x, v2.x, v3.x);
            *(float4*)&C[(size_t)n0*ldc + nb + c0 + 4] = make_float4(v4.x, v5.x, v6.x, v7.x);
        }
        if (n0 + 1 < M) {
            *(float4*)&C[(size_t)(n0+1)*ldc + nb + c0]     = make_float4(v0.y, v1.y, v2.y, v3.y);
            *(float4*)&C[(size_t)(n0+1)*ldc + nb + c0 + 4] = make_float4(v4.y, v5.y, v6.y, v7.y);
        }
    }
}

// ------------------------- per-step elementwise GRU v2 (float4, 16 lanes/node) -------------------------
__global__ __launch_bounds__(256)
void k_gru(int t,
           const float* __restrict__ gi_cur_t,
           const float* __restrict__ yring, const float* __restrict__ gring,
           const float* __restrict__ b_ih, const float* __restrict__ b_hh,
           float* __restrict__ out_t)
{
    int n  = blockIdx.x*16 + (threadIdx.x >> 4);
    int c0 = (threadIdx.x & 15) * 4;

    // attention softmax over window scores (zero frames have score 0, y = 0)
    float e2 = (t >= 1) ? gring[((t-1)%3)*NN + n] : 0.0f;
    float e1 = (t >= 1) ? ((t >= 2) ? gring[((t-2)%3)*NN + n] : 0.0f) : -1e30f;
    float e0 = (t >= 2) ? ((t >= 3) ? gring[((t-3)%3)*NN + n] : 0.0f) : -1e30f;
    float mx = fmaxf(e2, fmaxf(e1, e0));
    float a0 = (t >= 2) ? __expf(e0 - mx) : 0.f;
    float a1 = (t >= 1) ? __expf(e1 - mx) : 0.f;
    float a2 = __expf(e2 - mx);
    float inv = 1.0f / (a0 + a1 + a2);
    a0 *= inv; a1 *= inv; a2 *= inv;

    const float* gc = &gi_cur_t[(size_t)n*192];
    float4 gr = *(const float4*)&gc[c0];
    float4 gz = *(const float4*)&gc[64 + c0];
    float4 gn = *(const float4*)&gc[128 + c0];

    if (t >= 1) {
        const float* y = &yring[(size_t)((t-1)%3)*NN*192 + (size_t)n*192];
        float4 yr = *(const float4*)&y[c0];
        float4 yz = *(const float4*)&y[64 + c0];
        float4 yn = *(const float4*)&y[128 + c0];
        gr.x += a2*yr.x; gr.y += a2*yr.y; gr.z += a2*yr.z; gr.w += a2*yr.w;
        gz.x += a2*yz.x; gz.y += a2*yz.y; gz.z += a2*yz.z; gz.w += a2*yz.w;
        gn.x += a2*yn.x; gn.y += a2*yn.y; gn.z += a2*yn.z; gn.w += a2*yn.w;
    }
    if (t >= 2) {
        const float* y = &yring[(size_t)((t-2)%3)*NN*192 + (size_t)n*192];
        float4 yr = *(const float4*)&y[c0];
        float4 yz = *(const float4*)&y[64 + c0];
        float4 yn = *(const float4*)&y[128 + c0];
        gr.x += a1*yr.x; gr.y += a1*yr.y; gr.z += a1*yr.z; gr.w += a1*yr.w;
        gz.x += a1*yz.x; gz.y += a1*yz.y; gz.z += a1*yz.z; gz.w += a1*yz.w;
        gn.x += a1*yn.x; gn.y += a1*yn.y; gn.z += a1*yn.z; gn.w += a1*yn.w;
    }
    if (t >= 3) {
        const float* y = &yring[(size_t)((t-3)%3)*NN*192 + (size_t)n*192];
        float4 yr = *(const float4*)&y[c0];
        float4 yz = *(const float4*)&y[64 + c0];
        float4 yn = *(const float4*)&y[128 + c0];
        gr.x += a0*yr.x; gr.y += a0*yr.y; gr.z += a0*yr.z; gr.w += a0*yr.w;
        gz.x += a0*yz.x; gz.y += a0*yz.y; gz.z += a0*yz.z; gz.w += a0*yz.w;
        gn.x += a0*yn.x; gn.y += a0*yn.y; gn.z += a0*yn.z; gn.w += a0*yn.w;
    }

    float4 bir = *(const float4*)&b_ih[c0];
    float4 biz = *(const float4*)&b_ih[64 + c0];
    float4 bin = *(const float4*)&b_ih[128 + c0];
    float4 bhr = *(const float4*)&b_hh[c0];
    float4 bhz = *(const float4*)&b_hh[64 + c0];
    float4 bhn = *(const float4*)&b_hh[128 + c0];

    float4 H;
    {
        float r0 = sigf(gr.x + bir.x + bhr.x);
        float z0 = sigf(gz.x + biz.x + bhz.x);
        float n0 = tanhf(gn.x + bin.x + r0*bhn.x);
        H.x = (1.0f - z0) * n0;
    }
    {
        float r0 = sigf(gr.y + bir.y + bhr.y);
        float z0 = sigf(gz.y + biz.y + bhz.y);
        float n0 = tanhf(gn.y + bin.y + r0*bhn.y);
        H.y = (1.0f - z0) * n0;
    }
    {
        float r0 = sigf(gr.z + bir.z + bhr.z);
        float z0 = sigf(gz.z + biz.z + bhz.z);
        float n0 = tanhf(gn.z + bin.z + r0*bhn.z);
        H.z = (1.0f - z0) * n0;
    }
    {
        float r0 = sigf(gr.w + bir.w + bhr.w);
        float z0 = sigf(gz.w + biz.w + bhz.w);
        float n0 = tanhf(gn.w + bin.w + r0*bhn.w);
        H.w = (1.0f - z0) * n0;
    }
    *(float4*)&out_t[(size_t)n*64 + c0] = H;
}

// ------------------------- launcher -------------------------
extern "C" void kernel_launch(void* const* d_in, const int* in_sizes, int n_in,
                              void* d_out, int out_size)
{
    const float* xs    = (const float*)d_in[0];
    const int*   ei    = (const int*)  d_in[1];
    const float* W_gcn = (const float*)d_in[2];
    const float* b_gcn = (const float*)d_in[3];
    const float* Q     = (const float*)d_in[4];
    const float* r_vec = (const float*)d_in[5];
    const float* W_ih  = (const float*)d_in[6];
    const float* b_ih  = (const float*)d_in[8];
    const float* b_hh  = (const float*)d_in[9];
    float* out = (float*)d_out;

    float *p_xw, *p_cur, *p_gic, *p_yr, *p_gr, *p_dinv, *p_WcT, *p_WsQ;
    int   *p_cnt, *p_fill, *p_rp, *p_eb, *p_bs;
    cudaGetSymbolAddress((void**)&p_xw,   d_xw);
    cudaGetSymbolAddress((void**)&p_cur,  d_cur);
    cudaGetSymbolAddress((void**)&p_gic,  d_gicur);
    cudaGetSymbolAddress((void**)&p_yr,   d_yring);
    cudaGetSymbolAddress((void**)&p_gr,   d_gring);
    cudaGetSymbolAddress((void**)&p_dinv, d_dinv);
    cudaGetSymbolAddress((void**)&p_WcT,  d_WcT);
    cudaGetSymbolAddress((void**)&p_WsQ,  d_WsQ);
    cudaGetSymbolAddress((void**)&p_cnt,  d_cnt);
    cudaGetSymbolAddress((void**)&p_fill, d_fill);
    cudaGetSymbolAddress((void**)&p_rp,   d_rowptr);
    cudaGetSymbolAddress((void**)&p_eb,   d_ebuf);
    cudaGetSymbolAddress((void**)&p_bs,   d_bsum);

    cudaFuncSetAttribute(k_gemm, cudaFuncAttributeMaxDynamicSharedMemorySize, GSM_BYTES);

    const int nsb = (TN + 1023) / 1024;      // 586 scan blocks
    const int gx_big = (TN + BM - 1) / BM;   // 2344
    const int gx_y   = (NN + BM - 1) / BM;   // 196
    const int gx_gru = NN / 16;              // 3125

    cudaMemsetAsync(p_cnt, 0, (size_t)TN * sizeof(int));
    k_prep <<<1, 256>>>(W_ih, Q, p_WcT, p_WsQ);                              // launch 1
    k_count<<<dim3((EE + 255)/256, TT), 256>>>(ei, p_cnt);                   // launch 2

    // xw = xs @ W_gcn   [600000,128]x[128,64]
    k_gemm <<<dim3(gx_big, 1), 256, GSM_BYTES>>>(xs, W_gcn, p_xw, TN, FIN, HH, HH,
                                                 nullptr, nullptr);          // launch 3

    // DIAGNOSTIC at profiled slot 4: dummy k_gru(t=3). Reads stale scratch
    // (deterministic values); writes only out[3], which the real t=3 k_gru
    // below fully rewrites before any consumer reads it. Output unaffected.
    k_gru <<<gx_gru, 256>>>(3, p_gic + (size_t)3*NN*192, p_yr, p_gr,
                            b_ih, b_hh, out + (size_t)3*NN*64);              // launch 4

    k_scan1<<<nsb, 1024>>>(p_cnt, p_rp, p_bs, TN);                           // launch 5
    k_scan2<<<1, 1024>>>(p_bs, nsb);
    k_scan3<<<nsb, 1024>>>(p_cnt, p_rp, p_bs, p_fill, p_dinv, TN);
    k_fill <<<dim3((EE + 255)/256, TT), 256>>>(ei, p_fill, p_eb);

    k_gather<<<(TN + 7)/8, 256>>>(p_xw, b_gcn, p_cur, p_rp, p_cnt, p_dinv, p_eb);

    // gi_cur = cur @ W_c^T   [600000,64]x[64,192]
    k_gemm <<<dim3(gx_big, 3), 256, GSM_BYTES>>>(p_cur, p_WcT, p_gic, TN, HH, 192, 192,
                                                 nullptr, nullptr);

    for (int t = 0; t < TT; t++) {
        int slot = t % 3;
        k_gru<<<gx_gru, 256>>>(t, p_gic + (size_t)t*NN*192, p_yr, p_gr,
                               b_ih, b_hh, out + (size_t)t*NN*64);
        // y_t = h_t @ [Ws | Qt]; block-col 3 computes scores into gring
        k_gemm<<<dim3(gx_y, 4), 256, GSM_BYTES>>>(out + (size_t)t*NN*64, p_WsQ,
                                                  p_yr + (size_t)slot*NN*192, NN, HH, 256, 192,
                                                  p_gr + slot*NN, r_vec);
    }
}

// round 14
// speedup vs baseline: 1.3515x; 1.3515x over previous
#include <cuda_runtime.h>
#include <cstdint>

#define TT  12
#define NN  50000
#define EE  800000
#define TN  (TT*NN)          /* 600000 */
#define FIN 128
#define HH  64

// ------------------------- static device scratch -------------------------
__device__ float d_xw[(size_t)TN*64];          // xs @ W_gcn
__device__ float d_cur[(size_t)TN*64];         // GCN output
__device__ float d_gicur[(size_t)TN*192];      // cur @ W_ih[:, :64]^T
__device__ float d_yring[(size_t)3*NN*192];    // y = h @ Ws ring
__device__ float d_gring[3*NN];                // attention scalar ring
__device__ float d_dinv[TN];
__device__ int   d_cnt[TN];
__device__ int   d_fill[TN];
__device__ int   d_rowptr[TN];
__device__ int   d_ebuf[(size_t)TT*EE];
__device__ float d_WcT[64*192];                // [k][j] = W_ih[j][k]          (cur half)
__device__ float d_WsQ[64*256];                // [k][0..191]=W_ih[j][64+k]; [k][192+c]=Q[c][k]
__device__ int   d_bsum[1024];

// ------------------------- helpers -------------------------
__device__ __forceinline__ void ffma2(unsigned long long& d,
                                      unsigned long long a,
                                      unsigned long long b)
{
    asm("fma.rn.f32x2 %0, %1, %2, %0;" : "+l"(d) : "l"(a), "l"(b));
}

__device__ __forceinline__ float2 u2f2(unsigned long long u)
{
    float2 f;
    asm("mov.b64 {%0,%1}, %2;" : "=f"(f.x), "=f"(f.y) : "l"(u));
    return f;
}

__device__ __forceinline__ float sigf(float x)
{
    return 1.0f / (1.0f + __expf(-x));
}

// ------------------------- weight prep -------------------------
__global__ void k_prep(const float* __restrict__ W_ih, const float* __restrict__ Q,
                       float* __restrict__ WcT, float* __restrict__ WsQ)
{
    for (int i = threadIdx.x; i < 64*192; i += 256) {
        int k = i / 192, j = i % 192;
        WcT[(size_t)k*192 + j] = W_ih[(size_t)j*128 + k];
        WsQ[(size_t)k*256 + j] = W_ih[(size_t)j*128 + 64 + k];
    }
    for (int i = threadIdx.x; i < 64*64; i += 256) {
        int k = i / 64, c = i % 64;
        WsQ[(size_t)k*256 + 192 + c] = Q[(size_t)c*64 + k];
    }
}

// ------------------------- CSR build -------------------------
__global__ void k_count(const int* __restrict__ ei, int* __restrict__ cnt)
{
    int e = blockIdx.x*256 + threadIdx.x;
    int t = blockIdx.y;
    if (e < EE) {
        int dst = ei[(size_t)t*2*EE + EE + e];
        atomicAdd(&cnt[t*NN + dst], 1);
    }
}

__global__ void k_scan1(const int* __restrict__ cnt, int* __restrict__ incl,
                        int* __restrict__ bsum, int n)
{
    __shared__ int ws[32];
    int tid  = threadIdx.x;
    int i    = blockIdx.x*1024 + tid;
    int lane = tid & 31, wid = tid >> 5;
    int v = (i < n) ? cnt[i] : 0;
    int x = v;
#pragma unroll
    for (int o = 1; o < 32; o <<= 1) {
        int y = __shfl_up_sync(0xffffffffu, x, o);
        if (lane >= o) x += y;
    }
    if (lane == 31) ws[wid] = x;
    __syncthreads();
    if (wid == 0) {
        int s = ws[lane];
#pragma unroll
        for (int o = 1; o < 32; o <<= 1) {
            int y = __shfl_up_sync(0xffffffffu, s, o);
            if (lane >= o) s += y;
        }
        ws[lane] = s;
    }
    __syncthreads();
    if (wid > 0) x += ws[wid-1];
    if (i < n) incl[i] = x;
    if (tid == 1023) bsum[blockIdx.x] = x;
}

__global__ void k_scan2(int* __restrict__ bsum, int nb)
{
    __shared__ int ws[32];
    int tid  = threadIdx.x;
    int lane = tid & 31, wid = tid >> 5;
    int v = (tid < nb) ? bsum[tid] : 0;
    int x = v;
#pragma unroll
    for (int o = 1; o < 32; o <<= 1) {
        int y = __shfl_up_sync(0xffffffffu, x, o);
        if (lane >= o) x += y;
    }
    if (lane == 31) ws[wid] = x;
    __syncthreads();
    if (wid == 0) {
        int s = ws[lane];
#pragma unroll
        for (int o = 1; o < 32; o <<= 1) {
            int y = __shfl_up_sync(0xffffffffu, s, o);
            if (lane >= o) s += y;
        }
        ws[lane] = s;
    }
    __syncthreads();
    if (wid > 0) x += ws[wid-1];
    if (tid < nb) bsum[tid] = x - v;   // exclusive
}

__global__ void k_scan3(const int* __restrict__ cnt, int* __restrict__ incl_then_rowptr,
                        const int* __restrict__ bsum, int* __restrict__ fill,
                        float* __restrict__ dinv, int n)
{
    int i = blockIdx.x*1024 + threadIdx.x;
    if (i < n) {
        int c  = cnt[i];
        int ex = incl_then_rowptr[i] - c + bsum[blockIdx.x];
        incl_then_rowptr[i] = ex;
        fill[i] = ex;
        dinv[i] = rsqrtf(1.0f + (float)c);
    }
}

__global__ void k_fill(const int* __restrict__ ei, int* __restrict__ fill,
                       int* __restrict__ ebuf)
{
    int e = blockIdx.x*256 + threadIdx.x;
    int t = blockIdx.y;
    if (e < EE) {
        int src = ei[(size_t)t*2*EE + e];
        int dst = ei[(size_t)t*2*EE + EE + e];
        int pos = atomicAdd(&fill[t*NN + dst], 1);
        ebuf[pos] = t*NN + src;
    }
}

// ------------------------- gather (GCN aggregation), row range [0, M) -------------------------
__global__ void k_gather(const float* __restrict__ xw, const float* __restrict__ bg,
                         float* __restrict__ cur,
                         const int* __restrict__ rowptr, const int* __restrict__ cnt,
                         const float* __restrict__ dinv, const int* __restrict__ ebuf,
                         int M)
{
    int w    = blockIdx.x*8 + (threadIdx.x >> 5);
    int lane = threadIdx.x & 31;
    if (w >= M) return;
    int start = rowptr[w];
    int c     = cnt[w];
    int col   = 2*lane;
    float2 a0 = make_float2(0.f, 0.f), a1 = a0, a2 = a0, a3 = a0;
    for (int b0 = 0; b0 < c; b0 += 32) {
        int rem  = c - b0;
        int mcnt = rem < 32 ? rem : 32;
        int   idx = (lane < mcnt) ? ebuf[start + b0 + lane] : 0;
        float dv  = (lane < mcnt) ? dinv[idx] : 0.f;
        int e = 0;
        for (; e + 4 <= mcnt; e += 4) {
            int g0 = __shfl_sync(0xffffffffu, idx, e);
            int g1 = __shfl_sync(0xffffffffu, idx, e+1);
            int g2 = __shfl_sync(0xffffffffu, idx, e+2);
            int g3 = __shfl_sync(0xffffffffu, idx, e+3);
            float w0 = __shfl_sync(0xffffffffu, dv, e);
            float w1 = __shfl_sync(0xffffffffu, dv, e+1);
            float w2 = __shfl_sync(0xffffffffu, dv, e+2);
            float w3 = __shfl_sync(0xffffffffu, dv, e+3);
            float2 x0 = *(const float2*)&xw[(size_t)g0*64 + col];
            float2 x1 = *(const float2*)&xw[(size_t)g1*64 + col];
            float2 x2 = *(const float2*)&xw[(size_t)g2*64 + col];
            float2 x3 = *(const float2*)&xw[(size_t)g3*64 + col];
            a0.x += w0*x0.x; a0.y += w0*x0.y;
            a1.x += w1*x1.x; a1.y += w1*x1.y;
            a2.x += w2*x2.x; a2.y += w2*x2.y;
            a3.x += w3*x3.x; a3.y += w3*x3.y;
        }
        for (; e < mcnt; e++) {
            int   g  = __shfl_sync(0xffffffffu, idx, e);
            float wv = __shfl_sync(0xffffffffu, dv,  e);
            float2 x = *(const float2*)&xw[(size_t)g*64 + col];
            a0.x += wv*x.x; a0.y += wv*x.y;
        }
    }
    float ax = a0.x + a1.x + a2.x + a3.x;
    float ay = a0.y + a1.y + a2.y + a3.y;
    float ds = dinv[w];
    float2 s = *(const float2*)&xw[(size_t)w*64 + col];
    float2 o;
    o.x = ds*(ax + ds*s.x) + bg[col];
    o.y = ds*(ay + ds*s.y) + bg[col+1];
    *(float2*)&cur[(size_t)w*64 + col] = o;
}

// ------------------------- GEMM v7: round-10 core + nblk col-block loop (A-panel reuse) -------------------------
#define BM 256
#define ASTRIDE 260
#define AOFF(k, r) ((k)*ASTRIDE + ((r) ^ ((((k) >> 2) & 7) << 2)))
#define BPOS(cp) (4*(cp) + ((((cp)) >> 2) << 2))   /* dup col-pair float offset */
#define GSM_BYTES ((64*ASTRIDE + 64*160) * 4)      /* 107520 B */

__global__ __launch_bounds__(256, 2)
void k_gemm(const float* __restrict__ A, const float* __restrict__ B,
            float* __restrict__ C, int M, int K, int ldb, int ldc, int nblk,
            float* __restrict__ gbuf, const float* __restrict__ rv)
{
    extern __shared__ __align__(16) float smx[];
    float* As = smx;                    // [64][ASTRIDE] swizzled col-major
    float* Bs = smx + 64*ASTRIDE;       // [64][160] duplicated col pairs
    int tid   = threadIdx.x;
    int row0  = blockIdx.x * BM;
    int rbase = (tid >> 3) * 8;      // 8 rows (4 node pairs)
    int c0    = (tid & 7) * 8;       // 8 cols
    int cp0   = 4 * (tid & 7);       // col-pair base

    int wrp  = tid >> 5;
    int lane = tid & 31;
    int half = lane >> 4;
    int l4   = lane & 15;
    int sw   = (l4 & 7) << 2;

    for (int cb = 0; cb < nblk; cb++) {
        int nb = cb * 64;
        unsigned long long acc[4][8];
#pragma unroll
        for (int i = 0; i < 4; i++)
#pragma unroll
            for (int j = 0; j < 8; j++) acc[i][j] = 0ull;

        for (int kk = 0; kk < K; kk += 64) {
            if (kk | cb) __syncthreads();
            // A panel fill (skipped when reusing panel across col-blocks)
            if (cb == 0 || K > 64) {
#pragma unroll
                for (int rr = 0; rr < 16; rr += 4) {
                    float4 va[4];
#pragma unroll
                    for (int u = 0; u < 4; u++) {
                        int lr = wrp*32 + (rr + u)*2 + half;
                        int gr = row0 + lr;
                        va[u] = (gr < M) ? *(const float4*)&A[(size_t)gr*K + kk + 4*l4]
                                         : make_float4(0.f, 0.f, 0.f, 0.f);
                    }
#pragma unroll
                    for (int u = 0; u < 4; u++) {
                        int lr  = wrp*32 + (rr + u)*2 + half;
                        int rsw = lr ^ sw;
                        As[(4*l4 + 0)*ASTRIDE + rsw] = va[u].x;
                        As[(4*l4 + 1)*ASTRIDE + rsw] = va[u].y;
                        As[(4*l4 + 2)*ASTRIDE + rsw] = va[u].z;
                        As[(4*l4 + 3)*ASTRIDE + rsw] = va[u].w;
                    }
                }
            }
            // B panel: 64 rows x 64 cols, duplicated pairs
#pragma unroll
            for (int q = 0; q < 4; q++) {
                int idx = tid + q*256;
                int kb  = idx >> 4;
                int cq  = idx & 15;
                float4 w = *(const float4*)&B[(size_t)(kk + kb)*ldb + nb + cq*4];
                *(float4*)&Bs[kb*160 + BPOS(cq*2)]     = make_float4(w.x, w.x, w.y, w.y);
                *(float4*)&Bs[kb*160 + BPOS(cq*2 + 1)] = make_float4(w.z, w.z, w.w, w.w);
            }
            __syncthreads();
#pragma unroll
            for (int k = 0; k < 64; k++) {
                ulonglong2 a01 = *(const ulonglong2*)&As[AOFF(k, rbase)];
                ulonglong2 a23 = *(const ulonglong2*)&As[AOFF(k, rbase + 4)];
                ulonglong2 b0  = *(const ulonglong2*)&Bs[k*160 + BPOS(cp0)];
                ulonglong2 b1  = *(const ulonglong2*)&Bs[k*160 + BPOS(cp0) + 4];
                ulonglong2 b2  = *(const ulonglong2*)&Bs[k*160 + BPOS(cp0) + 8];
                ulonglong2 b3  = *(const ulonglong2*)&Bs[k*160 + BPOS(cp0) + 12];
                ffma2(acc[0][0], a01.x, b0.x); ffma2(acc[0][1], a01.x, b0.y);
                ffma2(acc[0][2], a01.x, b1.x); ffma2(acc[0][3], a01.x, b1.y);
                ffma2(acc[0][4], a01.x, b2.x); ffma2(acc[0][5], a01.x, b2.y);
                ffma2(acc[0][6], a01.x, b3.x); ffma2(acc[0][7], a01.x, b3.y);
                ffma2(acc[1][0], a01.y, b0.x); ffma2(acc[1][1], a01.y, b0.y);
                ffma2(acc[1][2], a01.y, b1.x); ffma2(acc[1][3], a01.y, b1.y);
                ffma2(acc[1][4], a01.y, b2.x); ffma2(acc[1][5], a01.y, b2.y);
                ffma2(acc[1][6], a01.y, b3.x); ffma2(acc[1][7], a01.y, b3.y);
                ffma2(acc[2][0], a23.x, b0.x); ffma2(acc[2][1], a23.x, b0.y);
                ffma2(acc[2][2], a23.x, b1.x); ffma2(acc[2][3], a23.x, b1.y);
                ffma2(acc[2][4], a23.x, b2.x); ffma2(acc[2][5], a23.x, b2.y);
                ffma2(acc[2][6], a23.x, b3.x); ffma2(acc[2][7], a23.x, b3.y);
                ffma2(acc[3][0], a23.y, b0.x); ffma2(acc[3][1], a23.y, b0.y);
                ffma2(acc[3][2], a23.y, b1.x); ffma2(acc[3][3], a23.y, b1.y);
                ffma2(acc[3][4], a23.y, b2.x); ffma2(acc[3][5], a23.y, b2.y);
                ffma2(acc[3][6], a23.y, b3.x); ffma2(acc[3][7], a23.y, b3.y);
            }
        }

        if (gbuf != nullptr && cb == 3) {
            // score epilogue: g = sum_c rv[c]*tanh(y2[c]); cols split over 8 lanes
            float rr[8];
#pragma unroll
            for (int j = 0; j < 8; j++) rr[j] = rv[c0 + j];
#pragma unroll
            for (int i = 0; i < 4; i++) {
                float px = 0.f, py = 0.f;
#pragma unroll
                for (int j = 0; j < 8; j++) {
                    float2 v = u2f2(acc[i][j]);
                    px += rr[j] * tanhf(v.x);
                    py += rr[j] * tanhf(v.y);
                }
                px += __shfl_down_sync(0xffffffffu, px, 4);
                py += __shfl_down_sync(0xffffffffu, py, 4);
                px += __shfl_down_sync(0xffffffffu, px, 2);
                py += __shfl_down_sync(0xffffffffu, py, 2);
                px += __shfl_down_sync(0xffffffffu, px, 1);
                py += __shfl_down_sync(0xffffffffu, py, 1);
                if ((tid & 7) == 0) {
                    int n0 = row0 + rbase + 2*i;
                    if (n0 < M)     gbuf[n0]     = px;
                    if (n0 + 1 < M) gbuf[n0 + 1] = py;
                }
            }
        } else {
#pragma unroll
            for (int i = 0; i < 4; i++) {
                int n0 = row0 + rbase + 2*i;
                float2 v0 = u2f2(acc[i][0]), v1 = u2f2(acc[i][1]);
                float2 v2 = u2f2(acc[i][2]), v3 = u2f2(acc[i][3]);
                float2 v4 = u2f2(acc[i][4]), v5 = u2f2(acc[i][5]);
                float2 v6 = u2f2(acc[i][6]), v7 = u2f2(acc[i][7]);
                if (n0 < M) {
                    *(float4*)&C[(size_t)n0*ldc + nb + c0]     = make_float4(v0.x, v1.x, v2.x, v3.x);
                    *(float4*)&C[(size_t)n0*ldc + nb + c0 + 4] = make_float4(v4.x, v5.x, v6.x, v7.x);
                }
                if (n0 + 1 < M) {
                    *(float4*)&C[(size_t)(n0+1)*ldc + nb + c0]     = make_float4(v0.y, v1.y, v2.y, v3.y);
                    *(float4*)&C[(size_t)(n0+1)*ldc + nb + c0 + 4] = make_float4(v4.y, v5.y, v6.y, v7.y);
                }
            }
        }
    }
}

// ------------------------- per-step elementwise GRU v2 (float4, 16 lanes/node) -------------------------
__global__ __launch_bounds__(256)
void k_gru(int t,
           const float* __restrict__ gi_cur_t,
           const float* __restrict__ yring, const float* __restrict__ gring,
           const float* __restrict__ b_ih, const float* __restrict__ b_hh,
           float* __restrict__ out_t)
{
    int n  = blockIdx.x*16 + (threadIdx.x >> 4);
    int c0 = (threadIdx.x & 15) * 4;

    float e2 = (t >= 1) ? gring[((t-1)%3)*NN + n] : 0.0f;
    float e1 = (t >= 1) ? ((t >= 2) ? gring[((t-2)%3)*NN + n] : 0.0f) : -1e30f;
    float e0 = (t >= 2) ? ((t >= 3) ? gring[((t-3)%3)*NN + n] : 0.0f) : -1e30f;
    float mx = fmaxf(e2, fmaxf(e1, e0));
    float a0 = (t >= 2) ? __expf(e0 - mx) : 0.f;
    float a1 = (t >= 1) ? __expf(e1 - mx) : 0.f;
    float a2 = __expf(e2 - mx);
    float inv = 1.0f / (a0 + a1 + a2);
    a0 *= inv; a1 *= inv; a2 *= inv;

    const float* gc = &gi_cur_t[(size_t)n*192];
    float4 gr = *(const float4*)&gc[c0];
    float4 gz = *(const float4*)&gc[64 + c0];
    float4 gn = *(const float4*)&gc[128 + c0];

    if (t >= 1) {
        const float* y = &yring[(size_t)((t-1)%3)*NN*192 + (size_t)n*192];
        float4 yr = *(const float4*)&y[c0];
        float4 yz = *(const float4*)&y[64 + c0];
        float4 yn = *(const float4*)&y[128 + c0];
        gr.x += a2*yr.x; gr.y += a2*yr.y; gr.z += a2*yr.z; gr.w += a2*yr.w;
        gz.x += a2*yz.x; gz.y += a2*yz.y; gz.z += a2*yz.z; gz.w += a2*yz.w;
        gn.x += a2*yn.x; gn.y += a2*yn.y; gn.z += a2*yn.z; gn.w += a2*yn.w;
    }
    if (t >= 2) {
        const float* y = &yring[(size_t)((t-2)%3)*NN*192 + (size_t)n*192];
        float4 yr = *(const float4*)&y[c0];
        float4 yz = *(const float4*)&y[64 + c0];
        float4 yn = *(const float4*)&y[128 + c0];
        gr.x += a1*yr.x; gr.y += a1*yr.y; gr.z += a1*yr.z; gr.w += a1*yr.w;
        gz.x += a1*yz.x; gz.y += a1*yz.y; gz.z += a1*yz.z; gz.w += a1*yz.w;
        gn.x += a1*yn.x; gn.y += a1*yn.y; gn.z += a1*yn.z; gn.w += a1*yn.w;
    }
    if (t >= 3) {
        const float* y = &yring[(size_t)((t-3)%3)*NN*192 + (size_t)n*192];
        float4 yr = *(const float4*)&y[c0];
        float4 yz = *(const float4*)&y[64 + c0];
        float4 yn = *(const float4*)&y[128 + c0];
        gr.x += a0*yr.x; gr.y += a0*yr.y; gr.z += a0*yr.z; gr.w += a0*yr.w;
        gz.x += a0*yz.x; gz.y += a0*yz.y; gz.z += a0*yz.z; gz.w += a0*yz.w;
        gn.x += a0*yn.x; gn.y += a0*yn.y; gn.z += a0*yn.z; gn.w += a0*yn.w;
    }

    float4 bir = *(const float4*)&b_ih[c0];
    float4 biz = *(const float4*)&b_ih[64 + c0];
    float4 bin = *(const float4*)&b_ih[128 + c0];
    float4 bhr = *(const float4*)&b_hh[c0];
    float4 bhz = *(const float4*)&b_hh[64 + c0];
    float4 bhn = *(const float4*)&b_hh[128 + c0];

    float4 H;
    {
        float r0 = sigf(gr.x + bir.x + bhr.x);
        float z0 = sigf(gz.x + biz.x + bhz.x);
        float n0 = tanhf(gn.x + bin.x + r0*bhn.x);
        H.x = (1.0f - z0) * n0;
    }
    {
        float r0 = sigf(gr.y + bir.y + bhr.y);
        float z0 = sigf(gz.y + biz.y + bhz.y);
        float n0 = tanhf(gn.y + bin.y + r0*bhn.y);
        H.y = (1.0f - z0) * n0;
    }
    {
        float r0 = sigf(gr.z + bir.z + bhr.z);
        float z0 = sigf(gz.z + biz.z + bhz.z);
        float n0 = tanhf(gn.z + bin.z + r0*bhn.z);
        H.z = (1.0f - z0) * n0;
    }
    {
        float r0 = sigf(gr.w + bir.w + bhr.w);
        float z0 = sigf(gz.w + biz.w + bhz.w);
        float n0 = tanhf(gn.w + bin.w + r0*bhn.w);
        H.w = (1.0f - z0) * n0;
    }
    *(float4*)&out_t[(size_t)n*64 + c0] = H;
}

// ------------------------- launcher -------------------------
extern "C" void kernel_launch(void* const* d_in, const int* in_sizes, int n_in,
                              void* d_out, int out_size)
{
    const float* xs    = (const float*)d_in[0];
    const int*   ei    = (const int*)  d_in[1];
    const float* W_gcn = (const float*)d_in[2];
    const float* b_gcn = (const float*)d_in[3];
    const float* Q     = (const float*)d_in[4];
    const float* r_vec = (const float*)d_in[5];
    const float* W_ih  = (const float*)d_in[6];
    const float* b_ih  = (const float*)d_in[8];
    const float* b_hh  = (const float*)d_in[9];
    float* out = (float*)d_out;

    float *p_xw, *p_cur, *p_gic, *p_yr, *p_gr, *p_dinv, *p_WcT, *p_WsQ;
    int   *p_cnt, *p_fill, *p_rp, *p_eb, *p_bs;
    cudaGetSymbolAddress((void**)&p_xw,   d_xw);
    cudaGetSymbolAddress((void**)&p_cur,  d_cur);
    cudaGetSymbolAddress((void**)&p_gic,  d_gicur);
    cudaGetSymbolAddress((void**)&p_yr,   d_yring);
    cudaGetSymbolAddress((void**)&p_gr,   d_gring);
    cudaGetSymbolAddress((void**)&p_dinv, d_dinv);
    cudaGetSymbolAddress((void**)&p_WcT,  d_WcT);
    cudaGetSymbolAddress((void**)&p_WsQ,  d_WsQ);
    cudaGetSymbolAddress((void**)&p_cnt,  d_cnt);
    cudaGetSymbolAddress((void**)&p_fill, d_fill);
    cudaGetSymbolAddress((void**)&p_rp,   d_rowptr);
    cudaGetSymbolAddress((void**)&p_eb,   d_ebuf);
    cudaGetSymbolAddress((void**)&p_bs,   d_bsum);

    cudaFuncSetAttribute(k_gemm, cudaFuncAttributeMaxDynamicSharedMemorySize, GSM_BYTES);

    const int nsb = (TN + 1023) / 1024;      // 586 scan blocks
    const int gx_big = (TN + BM - 1) / BM;   // 2344
    const int gx_y   = (NN + BM - 1) / BM;   // 196
    const int gx_gru = NN / 16;              // 3125

    cudaMemsetAsync(p_cnt, 0, (size_t)TN * sizeof(int));
    k_prep <<<1, 256>>>(W_ih, Q, p_WcT, p_WsQ);                              // launch 1
    k_count<<<dim3((EE + 255)/256, TT), 256>>>(ei, p_cnt);                   // launch 2

    // xw = xs @ W_gcn   [600000,128]x[128,64]
    k_gemm <<<gx_big, 256, GSM_BYTES>>>(xs, W_gcn, p_xw, TN, FIN, HH, HH, 1,
                                        nullptr, nullptr);                   // launch 3

    // DIAGNOSTIC at profiled slot 4: dummy k_gather over the t=0 slice (NN
    // rows, ~1/12 of the full gather). First run sees zero-initialized
    // cnt/rowptr (c=0 -> no edge reads, no OOB); later replays see the
    // previous replay's deterministic CSR. Its only writes (d_cur[0..NN)) are
    // fully rewritten by the real gather below. Output unaffected.
    k_gather<<<(NN + 7)/8, 256>>>(p_xw, b_gcn, p_cur, p_rp, p_cnt, p_dinv,
                                  p_eb, NN);                                 // launch 4

    k_scan1<<<nsb, 1024>>>(p_cnt, p_rp, p_bs, TN);                           // launch 5
    k_scan2<<<1, 1024>>>(p_bs, nsb);
    k_scan3<<<nsb, 1024>>>(p_cnt, p_rp, p_bs, p_fill, p_dinv, TN);
    k_fill <<<dim3((EE + 255)/256, TT), 256>>>(ei, p_fill, p_eb);

    k_gather<<<(TN + 7)/8, 256>>>(p_xw, b_gcn, p_cur, p_rp, p_cnt, p_dinv,
                                  p_eb, TN);

    // gi_cur = cur @ W_c^T   [600000,64]x[64,192] — A panel reused across 3 col-blocks
    k_gemm <<<gx_big, 256, GSM_BYTES>>>(p_cur, p_WcT, p_gic, TN, HH, 192, 192, 3,
                                        nullptr, nullptr);

    for (int t = 0; t < TT; t++) {
        int slot = t % 3;
        k_gru<<<gx_gru, 256>>>(t, p_gic + (size_t)t*NN*192, p_yr, p_gr,
                               b_ih, b_hh, out + (size_t)t*NN*64);
        // y_t = h_t @ [Ws | Qt]; A panel reused across 4 col-blocks; cb 3 -> scores
        k_gemm<<<gx_y, 256, GSM_BYTES>>>(out + (size_t)t*NN*64, p_WsQ,
                                         p_yr + (size_t)slot*NN*192, NN, HH, 256, 192, 4,
                                         p_gr + slot*NN, r_vec);
    }
}